// round 5
// baseline (speedup 1.0000x reference)
#include <cuda_runtime.h>
#include <cstdint>

#define OUTF   11008
#define INF    4096
#define BATCHN 16
#define SPLITK 32
#define KC     (INF / SPLITK)        // 128 k per CTA
#define KTILE  16                    // k per pipeline stage
#define NSTAGE (KC / KTILE)          // 8 stages
#define NBUF   4                     // smem buffers, 3 stages in flight
#define OTILE  256                   // output rows per CTA
#define NTHR   128                   // 2 rows per thread
#define WROW   20                    // padded ints per smem W row (80B)
#define WBUF   (OTILE * WROW)        // 5120 ints per buffer
#define XROW   20                    // padded floats per xs row
#define SMEM_BYTES (NBUF * WBUF * 4 + KC * XROW * 4)   // 81920 + 10240 = 92160

// Split-K partials: [SPLITK][BATCHN][OUTF] = 22.5 MB
__device__ float g_partial[SPLITK * BATCHN * OUTF];
// Phase-1 reduced partials: [4][BATCHN][OUTF] = 2.8 MB
__device__ float g_p2[4 * BATCHN * OUTF];

__device__ __forceinline__ unsigned long long dup_f2(float f) {
    unsigned long long r;
    asm("mov.b64 %0, {%1, %1};" : "=l"(r) : "f"(f));
    return r;
}
__device__ __forceinline__ void fma_f32x2(unsigned long long& d,
                                          unsigned long long a,
                                          unsigned long long b) {
    asm("fma.rn.f32x2 %0, %1, %2, %0;" : "+l"(d) : "l"(a), "l"(b));
}
__device__ __forceinline__ float2 unpack_f2(unsigned long long v) {
    float2 r;
    asm("mov.b64 {%0, %1}, %2;" : "=f"(r.x), "=f"(r.y) : "l"(v));
    return r;
}
__device__ __forceinline__ void cp_async16(unsigned smem_addr, const void* gptr) {
    asm volatile("cp.async.cg.shared.global [%0], [%1], 16;\n"
                 :: "r"(smem_addr), "l"(gptr));
}
__device__ __forceinline__ void cp_commit() {
    asm volatile("cp.async.commit_group;\n" ::: "memory");
}
__device__ __forceinline__ void cp_wait2() {
    asm volatile("cp.async.wait_group 2;\n" ::: "memory");
}

__global__ __launch_bounds__(NTHR) void qlinear_main(
    const float* __restrict__ x,
    const int*   __restrict__ w,
    const float* __restrict__ scale)
{
    extern __shared__ int sm[];
    int*   ws = sm;                          // NBUF x WBUF ints
    float* xs = (float*)(sm + NBUF * WBUF);  // KC x XROW floats

    const int tid   = threadIdx.x;
    const int obase = blockIdx.x * OTILE;
    const int kbase = blockIdx.y * KC;

    // ---- coalesced W staging: warp = 8 rows x 4 chunks of 16B ----
    const int row0  = tid >> 2;              // 0..31
    const int chunk = tid & 3;               // 0..3
    const int* gsrc_base = w + (size_t)(obase + row0) * INF + kbase + chunk * 4;
    const unsigned sdst_base =
        (unsigned)__cvta_generic_to_shared(ws + row0 * WROW + chunk * 4);

    // prologue: issue stages 0,1,2 into buffers 0,1,2
    #pragma unroll
    for (int s = 0; s < 3; ++s) {
        const int* g = gsrc_base + s * KTILE;
        const unsigned sd = sdst_base + (unsigned)(s * WBUF * 4);
        #pragma unroll
        for (int i = 0; i < 8; ++i)           // 8 x 32-row groups
            cp_async16(sd + (unsigned)(i * 32 * WROW * 4),
                       g + (size_t)i * 32 * INF);
        cp_commit();
    }

    // ---- stage x chunk transposed into smem (overlaps with cp.async) ----
    #pragma unroll
    for (int i = 0; i < (BATCHN * KC) / NTHR; ++i) {   // 16 elems/thread
        int e = tid + i * NTHR;
        int b = e >> 7;                  // / KC(128)
        int k = e & (KC - 1);
        xs[k * XROW + b] = x[b * INF + kbase + k];
    }

    const int o0 = obase + 2 * tid;
    const int o1 = o0 + 1;

    unsigned long long acc0[8], acc1[8];
    #pragma unroll
    for (int i = 0; i < 8; ++i) { acc0[i] = 0ULL; acc1[i] = 0ULL; }

    #pragma unroll 1
    for (int s = 0; s < NSTAGE; ++s) {
        cp_wait2();            // stages <= s complete (<=2 groups pending)
        __syncthreads();       // all threads done with buf[(s-1)%4], stage s visible

        // issue stage s+3 into buf[(s+3)%4] (== buf[(s-1)%4], now free)
        if (s + 3 < NSTAGE) {
            const int bi = (s + 3) & (NBUF - 1);
            const int* g = gsrc_base + (s + 3) * KTILE;
            const unsigned sd = sdst_base + (unsigned)(bi * WBUF * 4);
            #pragma unroll
            for (int i = 0; i < 8; ++i)
                cp_async16(sd + (unsigned)(i * 32 * WROW * 4),
                           g + (size_t)i * 32 * INF);
        }
        cp_commit();           // empty commit on tail stages keeps bookkeeping

        const int* wrow = ws + (s & (NBUF - 1)) * WBUF + (2 * tid) * WROW;

        #pragma unroll
        for (int j8 = 0; j8 < KTILE / 8; ++j8) {
            int4 a00 = *(const int4*)(wrow + j8 * 8);
            int4 a01 = *(const int4*)(wrow + j8 * 8 + 4);
            int4 a10 = *(const int4*)(wrow + WROW + j8 * 8);
            int4 a11 = *(const int4*)(wrow + WROW + j8 * 8 + 4);

            const int w0[8] = {a00.x, a00.y, a00.z, a00.w, a01.x, a01.y, a01.z, a01.w};
            const int w1[8] = {a10.x, a10.y, a10.z, a10.w, a11.x, a11.y, a11.z, a11.w};
            const int kb = s * KTILE + j8 * 8;

            #pragma unroll
            for (int j = 0; j < 8; ++j) {
                unsigned long long d0 = dup_f2((float)w0[j]);
                unsigned long long d1 = dup_f2((float)w1[j]);
                const ulonglong2* xr = (const ulonglong2*)(xs + (kb + j) * XROW);
                ulonglong2 xa = xr[0];
                ulonglong2 xb = xr[1];
                ulonglong2 xc = xr[2];
                ulonglong2 xd = xr[3];
                fma_f32x2(acc0[0], d0, xa.x);  fma_f32x2(acc1[0], d1, xa.x);
                fma_f32x2(acc0[1], d0, xa.y);  fma_f32x2(acc1[1], d1, xa.y);
                fma_f32x2(acc0[2], d0, xb.x);  fma_f32x2(acc1[2], d1, xb.x);
                fma_f32x2(acc0[3], d0, xb.y);  fma_f32x2(acc1[3], d1, xb.y);
                fma_f32x2(acc0[4], d0, xc.x);  fma_f32x2(acc1[4], d1, xc.x);
                fma_f32x2(acc0[5], d0, xc.y);  fma_f32x2(acc1[5], d1, xc.y);
                fma_f32x2(acc0[6], d0, xd.x);  fma_f32x2(acc1[6], d1, xd.x);
                fma_f32x2(acc0[7], d0, xd.y);  fma_f32x2(acc1[7], d1, xd.y);
            }
        }
    }

    // ---- epilogue: scale and write split-K partials ----
    const float s0 = scale[o0];
    const float s1 = scale[o1];
    float* pp = g_partial + (size_t)blockIdx.y * BATCHN * OUTF;

    #pragma unroll
    for (int p = 0; p < 8; ++p) {
        float2 v0 = unpack_f2(acc0[p]);
        float2 v1 = unpack_f2(acc1[p]);
        float2 r0 = make_float2(v0.x * s0, v1.x * s1);
        float2 r1 = make_float2(v0.y * s0, v1.y * s1);
        *(float2*)(pp + (size_t)(2 * p)     * OUTF + o0) = r0;
        *(float2*)(pp + (size_t)(2 * p + 1) * OUTF + o0) = r1;
    }
}

// Phase 1: 4 groups x (BATCHN*OUTF/4) float4 lanes; each thread sums 8 splits.
__global__ void qlinear_reduce1()
{
    const int n4 = BATCHN * OUTF / 4;        // 44032
    int t = blockIdx.x * blockDim.x + threadIdx.x;
    if (t >= 4 * n4) return;
    int g = t / n4;                          // split group 0..3
    int i = t - g * n4;

    const float4* gp = (const float4*)g_partial + (size_t)(8 * g) * n4 + i;
    float4 s = make_float4(0.f, 0.f, 0.f, 0.f);
    #pragma unroll
    for (int ky = 0; ky < 8; ++ky) {
        float4 p = gp[(size_t)ky * n4];
        s.x += p.x; s.y += p.y; s.z += p.z; s.w += p.w;
    }
    ((float4*)g_p2)[(size_t)g * n4 + i] = s;
}

// Phase 2: sum 4 group-partials + bias -> out.
__global__ void qlinear_reduce2(const float* __restrict__ bias,
                                float* __restrict__ out)
{
    const int n4 = BATCHN * OUTF / 4;
    int i = blockIdx.x * blockDim.x + threadIdx.x;
    if (i >= n4) return;
    int o4 = i % (OUTF / 4);
    float4 s = ((const float4*)bias)[o4];
    const float4* gp = (const float4*)g_p2;
    #pragma unroll
    for (int g = 0; g < 4; ++g) {
        float4 p = gp[(size_t)g * n4 + i];
        s.x += p.x; s.y += p.y; s.z += p.z; s.w += p.w;
    }
    ((float4*)out)[i] = s;
}

extern "C" void kernel_launch(void* const* d_in, const int* in_sizes, int n_in,
                              void* d_out, int out_size)
{
    const float* x     = (const float*)d_in[0];
    const int*   w     = (const int*)  d_in[1];
    const float* scale = (const float*)d_in[2];
    const float* bias  = (const float*)d_in[3];
    float* out = (float*)d_out;

    cudaFuncSetAttribute(qlinear_main,
                         cudaFuncAttributeMaxDynamicSharedMemorySize, SMEM_BYTES);

    dim3 grid(OUTF / OTILE, SPLITK);   // (43, 32) = 1376 CTAs
    qlinear_main<<<grid, NTHR, SMEM_BYTES>>>(x, w, scale);

    int t1 = 4 * (BATCHN * OUTF / 4);
    qlinear_reduce1<<<(t1 + 255) / 256, 256>>>();

    int t2 = BATCHN * OUTF / 4;
    qlinear_reduce2<<<(t2 + 255) / 256, 256>>>(bias, out);
}

// round 6
// speedup vs baseline: 1.1850x; 1.1850x over previous
#include <cuda_runtime.h>
#include <cstdint>

#define OUTF   11008
#define INF    4096
#define BATCHN 16
#define SPLITK 32
#define KC     (INF / SPLITK)        // 128 k per CTA
#define KTILE  16                    // k per pipeline stage
#define NSTAGE (KC / KTILE)          // 8 stages
#define NBUF   2
#define OTILE  256                   // output rows per CTA
#define NTHR   128                   // rows t and t+128 per thread
#define WROW   20                    // ints per smem W row (16 + 4 pad, conflict-free)
#define WBUF   (OTILE * WROW)        // 5120 ints per buffer
#define XROW   20
#define SMEM_BYTES (NBUF * WBUF * 4 + KC * XROW * 4)   // 40960 + 10240 = 51200

// Split-K partials: [SPLITK][BATCHN][OUTF] = 22.5 MB
__device__ float g_partial[SPLITK * BATCHN * OUTF];
// Phase-1 reduced partials: [4][BATCHN][OUTF] = 2.8 MB
__device__ float g_p2[4 * BATCHN * OUTF];

__device__ __forceinline__ unsigned long long dup_f2(float f) {
    unsigned long long r;
    asm("mov.b64 %0, {%1, %1};" : "=l"(r) : "f"(f));
    return r;
}
__device__ __forceinline__ void fma_f32x2(unsigned long long& d,
                                          unsigned long long a,
                                          unsigned long long b) {
    asm("fma.rn.f32x2 %0, %1, %2, %0;" : "+l"(d) : "l"(a), "l"(b));
}
__device__ __forceinline__ float2 unpack_f2(unsigned long long v) {
    float2 r;
    asm("mov.b64 {%0, %1}, %2;" : "=f"(r.x), "=f"(r.y) : "l"(v));
    return r;
}
__device__ __forceinline__ void cp_async16(unsigned smem_addr, const void* gptr) {
    asm volatile("cp.async.cg.shared.global [%0], [%1], 16;\n"
                 :: "r"(smem_addr), "l"(gptr));
}
__device__ __forceinline__ void cp_commit() {
    asm volatile("cp.async.commit_group;\n" ::: "memory");
}
__device__ __forceinline__ void cp_wait1() {
    asm volatile("cp.async.wait_group 1;\n" ::: "memory");
}

__global__ __launch_bounds__(NTHR) void qlinear_main(
    const float* __restrict__ x,
    const int*   __restrict__ w,
    const float* __restrict__ scale)
{
    extern __shared__ int sm[];
    int*   ws = sm;                          // NBUF x WBUF ints
    float* xs = (float*)(sm + NBUF * WBUF);  // KC x XROW floats

    const int tid   = threadIdx.x;
    const int obase = blockIdx.x * OTILE;
    const int kbase = blockIdx.y * KC;

    // ---- coalesced W staging: warp = 8 rows x 4 chunks of 16B ----
    const int row0  = tid >> 2;              // 0..31
    const int chunk = tid & 3;               // 0..3
    const int* gsrc_base = w + (size_t)(obase + row0) * INF + kbase + chunk * 4;
    const unsigned sdst_base =
        (unsigned)__cvta_generic_to_shared(ws + row0 * WROW + chunk * 4);

    // prologue: issue stages 0,1 into buffers 0,1
    #pragma unroll
    for (int s = 0; s < 2; ++s) {
        const int* g = gsrc_base + s * KTILE;
        const unsigned sd = sdst_base + (unsigned)(s * WBUF * 4);
        #pragma unroll
        for (int i = 0; i < 8; ++i)           // 8 x 32-row groups = 256 rows
            cp_async16(sd + (unsigned)(i * 32 * WROW * 4),
                       g + (size_t)i * 32 * INF);
        cp_commit();
    }

    // ---- stage x chunk transposed into smem (overlaps with cp.async) ----
    #pragma unroll
    for (int i = 0; i < (BATCHN * KC) / NTHR; ++i) {   // 16 elems/thread
        int e = tid + i * NTHR;
        int b = e >> 7;                  // / KC(128)
        int k = e & (KC - 1);
        xs[k * XROW + b] = x[b * INF + kbase + k];
    }

    // thread t owns rows obase+t and obase+t+128 (lane-consecutive => conflict-free LDS)
    const int o0 = obase + tid;
    const int o1 = o0 + 128;

    unsigned long long acc0[8], acc1[8];
    #pragma unroll
    for (int i = 0; i < 8; ++i) { acc0[i] = 0ULL; acc1[i] = 0ULL; }

    #pragma unroll 1
    for (int s = 0; s < NSTAGE; ++s) {
        cp_wait1();            // oldest pending group (stage s) complete
        __syncthreads();

        const int* wr0 = ws + (s & 1) * WBUF + tid * WROW;          // row t
        const int* wr1 = wr0 + 128 * WROW;                          // row t+128

        #pragma unroll
        for (int j8 = 0; j8 < KTILE / 8; ++j8) {
            int4 a00 = *(const int4*)(wr0 + j8 * 8);
            int4 a01 = *(const int4*)(wr0 + j8 * 8 + 4);
            int4 a10 = *(const int4*)(wr1 + j8 * 8);
            int4 a11 = *(const int4*)(wr1 + j8 * 8 + 4);

            const int w0[8] = {a00.x, a00.y, a00.z, a00.w, a01.x, a01.y, a01.z, a01.w};
            const int w1[8] = {a10.x, a10.y, a10.z, a10.w, a11.x, a11.y, a11.z, a11.w};
            const int kb = s * KTILE + j8 * 8;

            #pragma unroll
            for (int j = 0; j < 8; ++j) {
                unsigned long long d0 = dup_f2((float)w0[j]);
                unsigned long long d1 = dup_f2((float)w1[j]);
                const ulonglong2* xr = (const ulonglong2*)(xs + (kb + j) * XROW);
                ulonglong2 xa = xr[0];
                ulonglong2 xb = xr[1];
                ulonglong2 xc = xr[2];
                ulonglong2 xd = xr[3];
                fma_f32x2(acc0[0], d0, xa.x);  fma_f32x2(acc1[0], d1, xa.x);
                fma_f32x2(acc0[1], d0, xa.y);  fma_f32x2(acc1[1], d1, xa.y);
                fma_f32x2(acc0[2], d0, xb.x);  fma_f32x2(acc1[2], d1, xb.x);
                fma_f32x2(acc0[3], d0, xb.y);  fma_f32x2(acc1[3], d1, xb.y);
                fma_f32x2(acc0[4], d0, xc.x);  fma_f32x2(acc1[4], d1, xc.x);
                fma_f32x2(acc0[5], d0, xc.y);  fma_f32x2(acc1[5], d1, xc.y);
                fma_f32x2(acc0[6], d0, xd.x);  fma_f32x2(acc1[6], d1, xd.x);
                fma_f32x2(acc0[7], d0, xd.y);  fma_f32x2(acc1[7], d1, xd.y);
            }
        }
        __syncthreads();       // all threads done reading buf[s&1]

        // issue stage s+2 into buf[s&1]; always commit to keep accounting exact
        if (s + 2 < NSTAGE) {
            const int* g = gsrc_base + (s + 2) * KTILE;
            const unsigned sd = sdst_base + (unsigned)((s & 1) * WBUF * 4);
            #pragma unroll
            for (int i = 0; i < 8; ++i)
                cp_async16(sd + (unsigned)(i * 32 * WROW * 4),
                           g + (size_t)i * 32 * INF);
        }
        cp_commit();
    }

    // ---- epilogue: scale and write split-K partials ----
    const float s0 = scale[o0];
    const float s1 = scale[o1];
    float* pp = g_partial + (size_t)blockIdx.y * BATCHN * OUTF;

    #pragma unroll
    for (int p = 0; p < 8; ++p) {
        float2 v0 = unpack_f2(acc0[p]);   // batches (2p, 2p+1) for o0
        float2 v1 = unpack_f2(acc1[p]);   // batches (2p, 2p+1) for o1
        pp[(size_t)(2 * p)     * OUTF + o0] = v0.x * s0;
        pp[(size_t)(2 * p + 1) * OUTF + o0] = v0.y * s0;
        pp[(size_t)(2 * p)     * OUTF + o1] = v1.x * s1;
        pp[(size_t)(2 * p + 1) * OUTF + o1] = v1.y * s1;
    }
}

// Phase 1: 4 groups x (BATCHN*OUTF/4) float4 lanes; each thread sums 8 splits.
__global__ void qlinear_reduce1()
{
    const int n4 = BATCHN * OUTF / 4;        // 44032
    int t = blockIdx.x * blockDim.x + threadIdx.x;
    if (t >= 4 * n4) return;
    int g = t / n4;                          // split group 0..3
    int i = t - g * n4;

    const float4* gp = (const float4*)g_partial + (size_t)(8 * g) * n4 + i;
    float4 s = make_float4(0.f, 0.f, 0.f, 0.f);
    #pragma unroll
    for (int ky = 0; ky < 8; ++ky) {
        float4 p = gp[(size_t)ky * n4];
        s.x += p.x; s.y += p.y; s.z += p.z; s.w += p.w;
    }
    ((float4*)g_p2)[(size_t)g * n4 + i] = s;
}

// Phase 2: sum 4 group-partials + bias -> out.
__global__ void qlinear_reduce2(const float* __restrict__ bias,
                                float* __restrict__ out)
{
    const int n4 = BATCHN * OUTF / 4;
    int i = blockIdx.x * blockDim.x + threadIdx.x;
    if (i >= n4) return;
    int o4 = i % (OUTF / 4);
    float4 s = ((const float4*)bias)[o4];
    const float4* gp = (const float4*)g_p2;
    #pragma unroll
    for (int g = 0; g < 4; ++g) {
        float4 p = gp[(size_t)g * n4 + i];
        s.x += p.x; s.y += p.y; s.z += p.z; s.w += p.w;
    }
    ((float4*)out)[i] = s;
}

extern "C" void kernel_launch(void* const* d_in, const int* in_sizes, int n_in,
                              void* d_out, int out_size)
{
    const float* x     = (const float*)d_in[0];
    const int*   w     = (const int*)  d_in[1];
    const float* scale = (const float*)d_in[2];
    const float* bias  = (const float*)d_in[3];
    float* out = (float*)d_out;

    cudaFuncSetAttribute(qlinear_main,
                         cudaFuncAttributeMaxDynamicSharedMemorySize, SMEM_BYTES);

    dim3 grid(OUTF / OTILE, SPLITK);   // (43, 32) = 1376 CTAs, 4/SM resident
    qlinear_main<<<grid, NTHR, SMEM_BYTES>>>(x, w, scale);

    int t1 = 4 * (BATCHN * OUTF / 4);
    qlinear_reduce1<<<(t1 + 255) / 256, 256>>>();

    int t2 = BATCHN * OUTF / 4;
    qlinear_reduce2<<<(t2 + 255) / 256, 256>>>(bias, out);
}

// round 7
// speedup vs baseline: 1.4275x; 1.2047x over previous
#include <cuda_runtime.h>
#include <cuda_bf16.h>
#include <cstdint>

#define OUTF   11008
#define INF    4096
#define BATCHN 16
#define SPLITK 32
#define KC     (INF / SPLITK)        // 128 k per CTA
#define KTILE  16                    // k per pipeline stage == one MMA k-step
#define NSTAGE (KC / KTILE)          // 8 stages
#define OTILE  256                   // output rows per CTA (4 warps x 64 rows)
#define NTHR   128
#define WROW   24                    // ints per smem W row (16 data + 8 pad; bank-disjoint LDS.64)
#define WBUF   (OTILE * WROW)        // 6144 ints per buffer
#define XSTR   68                    // words per xs row (64 data + 4 pad; conflict-free B loads)
#define XWORDS (16 * XSTR)           // one bf16 plane (hi or lo)
#define SMEM_WORDS (2 * WBUF + 2 * XWORDS)
#define SMEM_BYTES (SMEM_WORDS * 4)  // 57856 B -> 4 CTAs/SM

// Split-K partials: [SPLITK][BATCHN][OUTF] = 22.5 MB
__device__ float g_partial[SPLITK * BATCHN * OUTF];
// Phase-1 reduced partials: [4][BATCHN][OUTF]
__device__ float g_p2[4 * BATCHN * OUTF];

__device__ __forceinline__ void cp_async16(unsigned smem_addr, const void* gptr) {
    asm volatile("cp.async.cg.shared.global [%0], [%1], 16;\n"
                 :: "r"(smem_addr), "l"(gptr));
}
__device__ __forceinline__ void cp_commit() {
    asm volatile("cp.async.commit_group;\n" ::: "memory");
}
__device__ __forceinline__ void cp_wait1() {
    asm volatile("cp.async.wait_group 1;\n" ::: "memory");
}
// pack two floats into bf16x2: lo half = first arg (even k), hi half = second (odd k)
__device__ __forceinline__ uint32_t pack_bf16x2(float lo, float hi) {
    uint32_t r;
    asm("cvt.rn.bf16x2.f32 %0, %1, %2;" : "=r"(r) : "f"(hi), "f"(lo));
    return r;
}
__device__ __forceinline__ void mma16816(float* c, const uint32_t* a, const uint32_t* b) {
    asm volatile(
        "mma.sync.aligned.m16n8k16.row.col.f32.bf16.bf16.f32 "
        "{%0,%1,%2,%3}, {%4,%5,%6,%7}, {%8,%9}, {%0,%1,%2,%3};"
        : "+f"(c[0]), "+f"(c[1]), "+f"(c[2]), "+f"(c[3])
        : "r"(a[0]), "r"(a[1]), "r"(a[2]), "r"(a[3]), "r"(b[0]), "r"(b[1]));
}

__global__ __launch_bounds__(NTHR, 4) void qlinear_main(
    const float* __restrict__ x,
    const int*   __restrict__ w,
    const float* __restrict__ scale)
{
    extern __shared__ int sm[];
    int*      ws  = sm;                         // 2 x WBUF ints (W, int32)
    uint32_t* xhw = (uint32_t*)(sm + 2 * WBUF); // 16 x XSTR words (x_hi bf16x2)
    uint32_t* xlw = xhw + XWORDS;               // 16 x XSTR words (x_lo bf16x2)

    const int tid   = threadIdx.x;
    const int obase = blockIdx.x * OTILE;
    const int kbase = blockIdx.y * KC;

    // ---- W staging addressing: warp = 8 rows x 4 chunks of 16B, coalesced ----
    const int row0  = tid >> 2;              // 0..31
    const int chunk = tid & 3;               // 0..3
    const int* gsrc_base = w + (size_t)(obase + row0) * INF + kbase + chunk * 4;
    const unsigned sdst_base =
        (unsigned)__cvta_generic_to_shared(ws + row0 * WROW + chunk * 4);

    // prologue: issue stages 0,1 into buffers 0,1
    #pragma unroll
    for (int s = 0; s < 2; ++s) {
        const int* g = gsrc_base + s * KTILE;
        const unsigned sd = sdst_base + (unsigned)(s * WBUF * 4);
        #pragma unroll
        for (int i = 0; i < 8; ++i)
            cp_async16(sd + (unsigned)(i * 32 * WROW * 4),
                       g + (size_t)i * 32 * INF);
        cp_commit();
    }

    // ---- stage x chunk as bf16 hi/lo planes, layout xs[b][kpair] ----
    {
        const int b   = tid >> 3;            // 0..15
        const int grp = tid & 7;             // 0..7 -> 16 k each
        const float* xp = x + (size_t)b * INF + kbase + grp * 16;
        uint32_t* xh = xhw + b * XSTR + grp * 8;
        uint32_t* xl = xlw + b * XSTR + grp * 8;
        #pragma unroll
        for (int q = 0; q < 4; ++q) {
            float4 v = ((const float4*)xp)[q];
            __nv_bfloat16 h0 = __float2bfloat16_rn(v.x);
            __nv_bfloat16 h1 = __float2bfloat16_rn(v.y);
            __nv_bfloat16 h2 = __float2bfloat16_rn(v.z);
            __nv_bfloat16 h3 = __float2bfloat16_rn(v.w);
            float l0 = v.x - __bfloat162float(h0);
            float l1 = v.y - __bfloat162float(h1);
            float l2 = v.z - __bfloat162float(h2);
            float l3 = v.w - __bfloat162float(h3);
            xh[q * 2]     = (uint32_t)__bfloat16_as_ushort(h0) |
                            ((uint32_t)__bfloat16_as_ushort(h1) << 16);
            xh[q * 2 + 1] = (uint32_t)__bfloat16_as_ushort(h2) |
                            ((uint32_t)__bfloat16_as_ushort(h3) << 16);
            xl[q * 2]     = pack_bf16x2(l0, l1);
            xl[q * 2 + 1] = pack_bf16x2(l2, l3);
        }
    }

    const int warp = tid >> 5;
    const int lane = tid & 31;
    const int g4   = lane >> 2;              // groupID 0..7
    const int t4   = lane & 3;               // threadID in group
    const int wofs = warp * 64;              // warp's row offset within tile

    float acc[4][2][4];                      // [m-tile][batch-half][c-regs]
    #pragma unroll
    for (int t = 0; t < 4; ++t)
        #pragma unroll
        for (int h = 0; h < 2; ++h)
            #pragma unroll
            for (int r = 0; r < 4; ++r) acc[t][h][r] = 0.f;

    #pragma unroll 1
    for (int s = 0; s < NSTAGE; ++s) {
        cp_wait1();
        __syncthreads();

        // ---- B fragments: x_hi / x_lo, both batch halves (conflict-free LDS) ----
        uint32_t bh[2][2], bl[2][2];
        #pragma unroll
        for (int h = 0; h < 2; ++h) {
            const int xrow = (g4 + 8 * h) * XSTR + 8 * s + t4;
            bh[h][0] = xhw[xrow];
            bh[h][1] = xhw[xrow + 4];
            bl[h][0] = xlw[xrow];
            bl[h][1] = xlw[xrow + 4];
        }

        const int* wbuf = ws + (s & 1) * WBUF;

        #pragma unroll
        for (int t = 0; t < 4; ++t) {
            const int r0 = wofs + t * 16 + g4;
            int2 w0 = *(const int2*)(wbuf + r0 * WROW + 2 * t4);
            int2 w1 = *(const int2*)(wbuf + (r0 + 8) * WROW + 2 * t4);
            int2 w2 = *(const int2*)(wbuf + r0 * WROW + 2 * t4 + 8);
            int2 w3 = *(const int2*)(wbuf + (r0 + 8) * WROW + 2 * t4 + 8);
            uint32_t a[4];
            a[0] = pack_bf16x2((float)w0.x, (float)w0.y);
            a[1] = pack_bf16x2((float)w1.x, (float)w1.y);
            a[2] = pack_bf16x2((float)w2.x, (float)w2.y);
            a[3] = pack_bf16x2((float)w3.x, (float)w3.y);
            mma16816(acc[t][0], a, bh[0]);
            mma16816(acc[t][0], a, bl[0]);
            mma16816(acc[t][1], a, bh[1]);
            mma16816(acc[t][1], a, bl[1]);
        }
        __syncthreads();

        // issue stage s+2 into buf[s&1]; always commit for exact accounting
        if (s + 2 < NSTAGE) {
            const int* g = gsrc_base + (s + 2) * KTILE;
            const unsigned sd = sdst_base + (unsigned)((s & 1) * WBUF * 4);
            #pragma unroll
            for (int i = 0; i < 8; ++i)
                cp_async16(sd + (unsigned)(i * 32 * WROW * 4),
                           g + (size_t)i * 32 * INF);
        }
        cp_commit();
    }

    // ---- epilogue: scale, write split-K partials ----
    float* pp = g_partial + (size_t)blockIdx.y * BATCHN * OUTF;
    #pragma unroll
    for (int t = 0; t < 4; ++t) {
        const int r0 = obase + wofs + t * 16 + g4;
        const int r1 = r0 + 8;
        const float s0 = scale[r0];
        const float s1 = scale[r1];
        #pragma unroll
        for (int h = 0; h < 2; ++h) {
            const int b0 = 2 * t4 + 8 * h;
            pp[(size_t)b0       * OUTF + r0] = acc[t][h][0] * s0;
            pp[(size_t)(b0 + 1) * OUTF + r0] = acc[t][h][1] * s0;
            pp[(size_t)b0       * OUTF + r1] = acc[t][h][2] * s1;
            pp[(size_t)(b0 + 1) * OUTF + r1] = acc[t][h][3] * s1;
        }
    }
}

// Phase 1: 4 groups x (BATCHN*OUTF/4) float4 lanes; each thread sums 8 splits.
__global__ void qlinear_reduce1()
{
    const int n4 = BATCHN * OUTF / 4;        // 44032
    int t = blockIdx.x * blockDim.x + threadIdx.x;
    if (t >= 4 * n4) return;
    int g = t / n4;
    int i = t - g * n4;

    const float4* gp = (const float4*)g_partial + (size_t)(8 * g) * n4 + i;
    float4 s = make_float4(0.f, 0.f, 0.f, 0.f);
    #pragma unroll
    for (int ky = 0; ky < 8; ++ky) {
        float4 p = gp[(size_t)ky * n4];
        s.x += p.x; s.y += p.y; s.z += p.z; s.w += p.w;
    }
    ((float4*)g_p2)[(size_t)g * n4 + i] = s;
}

// Phase 2: sum 4 group-partials + bias -> out.
__global__ void qlinear_reduce2(const float* __restrict__ bias,
                                float* __restrict__ out)
{
    const int n4 = BATCHN * OUTF / 4;
    int i = blockIdx.x * blockDim.x + threadIdx.x;
    if (i >= n4) return;
    int o4 = i % (OUTF / 4);
    float4 s = ((const float4*)bias)[o4];
    const float4* gp = (const float4*)g_p2;
    #pragma unroll
    for (int g = 0; g < 4; ++g) {
        float4 p = gp[(size_t)g * n4 + i];
        s.x += p.x; s.y += p.y; s.z += p.z; s.w += p.w;
    }
    ((float4*)out)[i] = s;
}

extern "C" void kernel_launch(void* const* d_in, const int* in_sizes, int n_in,
                              void* d_out, int out_size)
{
    const float* x     = (const float*)d_in[0];
    const int*   w     = (const int*)  d_in[1];
    const float* scale = (const float*)d_in[2];
    const float* bias  = (const float*)d_in[3];
    float* out = (float*)d_out;

    cudaFuncSetAttribute(qlinear_main,
                         cudaFuncAttributeMaxDynamicSharedMemorySize, SMEM_BYTES);

    dim3 grid(OUTF / OTILE, SPLITK);   // (43, 32) = 1376 CTAs
    qlinear_main<<<grid, NTHR, SMEM_BYTES>>>(x, w, scale);

    int t1 = 4 * (BATCHN * OUTF / 4);
    qlinear_reduce1<<<(t1 + 255) / 256, 256>>>();

    int t2 = BATCHN * OUTF / 4;
    qlinear_reduce2<<<(t2 + 255) / 256, 256>>>(bias, out);
}